// round 5
// baseline (speedup 1.0000x reference)
#include <cuda_runtime.h>
#include <math.h>

// Problem constants
#define BB   256
#define TT   512
#define IND  128
#define NI   149
#define NC   99
#define NM   8
#define CAT0 (IND + NI)   // 277
#define CAT1 (NI + NC)    // 248
#define CAT2 (NC + NM)    // 107
#define S0   160          // padded j-stride layer0
#define S1   128          // padded j-stride layer1
#define S2   8            // j-stride layer2
#define ROWS 4
#define NTH  480

// SMEM layout (floats)
#define OFF_XH0   0                 // 277*8 = 2216 (dup: a0,a0,a1,a1,a2,a2,a3,a3)
#define OFF_XH1   2216              // 248*8 = 1984
#define OFF_XH2   4200              // 110*4 = 440  (plain [k][4rows])
#define OFF_PART  4640              // 9216
#define OFF_PART2 13856             // 3*160*4 = 1920
#define OFF_SW2   15776             // 3*107*8 = 2568
#define SMEM_FLOATS 18344
#define SMEM_BYTES  (SMEM_FLOATS * 4)

// Precomputed fused/masked/transposed weights (padded j zeroed)
__device__ float g_W0[3][CAT0 * S0];
__device__ float g_W1[3][CAT1 * S1];
__device__ float g_W2[3][CAT2 * S2];
__device__ float g_bc[NI + NC + NM];

// ---------------------------------------------------------------------------
__global__ void cfc_precompute_kernel(
    const float* __restrict__ w1_0, const float* __restrict__ w2_0,
    const float* __restrict__ wa_0, const float* __restrict__ wb_0,
    const float* __restrict__ ba_0, const float* __restrict__ bb_0,
    const int*   __restrict__ m0,
    const float* __restrict__ w1_1, const float* __restrict__ w2_1,
    const float* __restrict__ wa_1, const float* __restrict__ wb_1,
    const float* __restrict__ ba_1, const float* __restrict__ bb_1,
    const int*   __restrict__ m1,
    const float* __restrict__ w1_2, const float* __restrict__ w2_2,
    const float* __restrict__ wa_2, const float* __restrict__ wb_2,
    const float* __restrict__ ba_2, const float* __restrict__ bb_2,
    const int*   __restrict__ m2,
    const float* __restrict__ dt)
{
    const float ts = dt[0];
    const int idx    = blockIdx.x * blockDim.x + threadIdx.x;
    const int stride = gridDim.x * blockDim.x;

    for (int i = idx; i < CAT0 * S0; i += stride) {
        int k = i / S0, j = i - k * S0;
        float v1 = 0.f, v2 = 0.f, vc = 0.f;
        if (j < NI) {
            int src = j * CAT0 + k;
            float mm = (float)m0[src];
            v1 = w1_0[src] * mm;
            v2 = w2_0[src] * mm;
            vc = ts * wa_0[src] + wb_0[src];
        }
        g_W0[0][i] = v1; g_W0[1][i] = v2; g_W0[2][i] = vc;
    }
    for (int i = idx; i < CAT1 * S1; i += stride) {
        int k = i / S1, j = i - k * S1;
        float v1 = 0.f, v2 = 0.f, vc = 0.f;
        if (j < NC) {
            int src = j * CAT1 + k;
            float mm = (float)m1[src];
            v1 = w1_1[src] * mm;
            v2 = w2_1[src] * mm;
            vc = ts * wa_1[src] + wb_1[src];
        }
        g_W1[0][i] = v1; g_W1[1][i] = v2; g_W1[2][i] = vc;
    }
    for (int i = idx; i < CAT2 * S2; i += stride) {
        int k = i / S2, j = i - k * S2;
        int src = j * CAT2 + k;
        float mm = (float)m2[src];
        g_W2[0][i] = w1_2[src] * mm;
        g_W2[1][i] = w2_2[src] * mm;
        g_W2[2][i] = ts * wa_2[src] + wb_2[src];
    }
    for (int j = idx; j < NI; j += stride) g_bc[j]           = ts * ba_0[j] + bb_0[j];
    for (int j = idx; j < NC; j += stride) g_bc[NI + j]      = ts * ba_1[j] + bb_1[j];
    for (int j = idx; j < NM; j += stride) g_bc[NI + NC + j] = ts * ba_2[j] + bb_2[j];
}

// ---------------------------------------------------------------------------
// Packed fp32x2 helpers
// ---------------------------------------------------------------------------
__device__ __forceinline__ unsigned long long pack2(float a, float b) {
    unsigned long long r;
    asm("mov.b64 %0, {%1, %2};" : "=l"(r) : "f"(a), "f"(b));
    return r;
}
__device__ __forceinline__ void unpack2(unsigned long long v, float& a, float& b) {
    asm("mov.b64 {%0, %1}, %2;" : "=f"(a), "=f"(b) : "l"(v));
}
__device__ __forceinline__ unsigned long long fma2(unsigned long long a,
                                                   unsigned long long b,
                                                   unsigned long long c) {
    unsigned long long d;
    asm("fma.rn.f32x2 %0, %1, %2, %3;" : "=l"(d) : "l"(a), "l"(b), "l"(c));
    return d;
}
__device__ __forceinline__ unsigned long long add2(unsigned long long a,
                                                   unsigned long long b) {
    unsigned long long d;
    asm("add.rn.f32x2 %0, %1, %2;" : "=l"(d) : "l"(a), "l"(b));
    return d;
}
__device__ __forceinline__ float sigmoidf_(float z) { return 1.0f / (1.0f + expf(-z)); }
__device__ __forceinline__ float cfc_mix(float a1, float a2, float ac,
                                         float b1, float b2, float bc) {
    float ff1 = tanhf(a1 + b1);
    float ff2 = tanhf(a2 + b2);
    float ti  = sigmoidf_(ac + bc);
    return ff1 + ti * (ff2 - ff1);
}

// ---------------------------------------------------------------------------
// Main persistent kernel: 64 CTAs x 480 threads, 4 batch rows each.
// Matmul thread = (mat, j-group-of-4, k-chunk); LDG.128 weights; 8 FFMA2/k.
// ---------------------------------------------------------------------------
__global__ __launch_bounds__(NTH, 1) void cfc_main_kernel(
    const float* __restrict__ x,
    const float* __restrict__ b1_0, const float* __restrict__ b2_0,
    const float* __restrict__ b1_1, const float* __restrict__ b2_1,
    const float* __restrict__ b1_2, const float* __restrict__ b2_2,
    float* __restrict__ out, int write_h)
{
    extern __shared__ float sm[];
    float* xh0d  = sm + OFF_XH0;
    float* xh1d  = sm + OFF_XH1;
    float* xh2   = sm + OFF_XH2;
    float* part  = sm + OFF_PART;
    float* part2 = sm + OFF_PART2;
    float* sw2   = sm + OFF_SW2;

    const int tid = threadIdx.x;
    const int b0  = blockIdx.x * ROWS;
    const int mat = tid / 160;
    const int rem = tid - mat * 160;
    const int jj  = rem;
    const int rsel = (mat == 0) ? 0 : mat;

    // matmul decomposition
    const int jg0 = rem % 40, kc0 = rem / 40;
    const int kb0 = kc0 * 70;
    int ke0 = kb0 + 70; if (ke0 > CAT0) ke0 = CAT0;
    const int jg1 = rem % 25, kc1 = rem / 25;
    const int kb1 = kc1 * 42;
    int ke1 = kb1 + 42; if (ke1 > CAT1) ke1 = CAT1;
    const bool act1 = (kc1 < 6);

    // ---- prologue ----
    for (int i = tid; i < 2216; i += NTH) xh0d[i] = 0.f;
    for (int i = tid; i < 1984; i += NTH) xh1d[i] = 0.f;
    for (int i = tid; i < 440;  i += NTH) xh2[i]  = 0.f;
    for (int i = tid; i < 3 * CAT2 * S2; i += NTH) sw2[i] = ((const float*)g_W2)[i];

    float rb1_0 = 0.f, rb2_0 = 0.f, rbc_0 = 0.f;
    float rb1_1 = 0.f, rb2_1 = 0.f, rbc_1 = 0.f;
    float rb1_2 = 0.f, rb2_2 = 0.f, rbc_2 = 0.f;
    if (jj < NI) { rb1_0 = b1_0[jj]; rb2_0 = b2_0[jj]; rbc_0 = g_bc[jj]; }
    if (jj < NC) { rb1_1 = b1_1[jj]; rb2_1 = b2_1[jj]; rbc_1 = g_bc[NI + jj]; }
    if (jj < NM) { rb1_2 = b1_2[jj]; rb2_2 = b2_2[jj]; rbc_2 = g_bc[NI + NC + jj]; }

    // stage x_0 (duplicated), prefetch x_1
    const int i0 = tid, i1 = tid + NTH;
    for (int i = tid; i < ROWS * IND; i += NTH) {
        int r = i >> 7, k = i & 127;
        float v = x[((size_t)(b0 + r) * TT + 0) * IND + k];
        *(unsigned long long*)&xh0d[k * 8 + r * 2] = pack2(v, v);
    }
    float xr0 = x[((size_t)(b0 + (i0 >> 7)) * TT + 1) * IND + (i0 & 127)];
    float xr1 = 0.f;
    if (i1 < ROWS * IND)
        xr1 = x[((size_t)(b0 + (i1 >> 7)) * TT + 1) * IND + (i1 & 127)];
    __syncthreads();

    for (int t = 0; t < TT; ++t) {
        // ============ (a) layer-0 partials ============
        {
            const ulonglong2* Wp =
                (const ulonglong2*)(g_W0[mat] + (size_t)kb0 * S0 + jg0 * 4);
            unsigned long long aA0 = 0, aB0 = 0, aA1 = 0, aB1 = 0;
            unsigned long long aA2 = 0, aB2 = 0, aA3 = 0, aB3 = 0;
            const float* ab = xh0d + kb0 * 8;
            #pragma unroll 5
            for (int k = kb0; k < ke0; ++k) {
                ulonglong2 w = *Wp; Wp += (S0 / 4);
                ulonglong2 d01 = *(const ulonglong2*)(ab);
                ulonglong2 d23 = *(const ulonglong2*)(ab + 4);
                ab += 8;
                aA0 = fma2(w.x, d01.x, aA0); aB0 = fma2(w.y, d01.x, aB0);
                aA1 = fma2(w.x, d01.y, aA1); aB1 = fma2(w.y, d01.y, aB1);
                aA2 = fma2(w.x, d23.x, aA2); aB2 = fma2(w.y, d23.x, aB2);
                aA3 = fma2(w.x, d23.y, aA3); aB3 = fma2(w.y, d23.y, aB3);
            }
            float* P = part + (size_t)((kc0 * 3 + mat) * 4) * 160 + jg0 * 4;
            *(ulonglong2*)(P)       = make_ulonglong2(aA0, aB0);
            *(ulonglong2*)(P + 160) = make_ulonglong2(aA1, aB1);
            *(ulonglong2*)(P + 320) = make_ulonglong2(aA2, aB2);
            *(ulonglong2*)(P + 480) = make_ulonglong2(aA3, aB3);
        }
        __syncthreads();

        // ============ (c) combine layer-0 + x restage ============
        if (jj < NI) {
            float a1 = 0.f, a2 = 0.f, ac = 0.f;
            #pragma unroll
            for (int c = 0; c < 4; ++c) {
                a1 += part[((c * 3 + 0) * 4 + rsel) * 160 + jj];
                a2 += part[((c * 3 + 1) * 4 + rsel) * 160 + jj];
                ac += part[((c * 3 + 2) * 4 + rsel) * 160 + jj];
            }
            float h = cfc_mix(a1, a2, ac, rb1_0, rb2_0, rbc_0);
            unsigned long long hh = pack2(h, h);
            *(unsigned long long*)&xh0d[(IND + jj) * 8 + rsel * 2] = hh;
            *(unsigned long long*)&xh1d[jj * 8 + rsel * 2]         = hh;
            if (mat == 0) {
                float c1 = 0.f, c2 = 0.f, cc = 0.f;
                #pragma unroll
                for (int c = 0; c < 4; ++c) {
                    c1 += part[((c * 3 + 0) * 4 + 3) * 160 + jj];
                    c2 += part[((c * 3 + 1) * 4 + 3) * 160 + jj];
                    cc += part[((c * 3 + 2) * 4 + 3) * 160 + jj];
                }
                float h3 = cfc_mix(c1, c2, cc, rb1_0, rb2_0, rbc_0);
                unsigned long long hh3 = pack2(h3, h3);
                *(unsigned long long*)&xh0d[(IND + jj) * 8 + 6] = hh3;
                *(unsigned long long*)&xh1d[jj * 8 + 6]         = hh3;
            }
        }
        {
            *(unsigned long long*)&xh0d[(i0 & 127) * 8 + (i0 >> 7) * 2] = pack2(xr0, xr0);
            if (i1 < ROWS * IND)
                *(unsigned long long*)&xh0d[(i1 & 127) * 8 + (i1 >> 7) * 2] = pack2(xr1, xr1);
            int tn = t + 2; if (tn > TT - 1) tn = TT - 1;
            xr0 = x[((size_t)(b0 + (i0 >> 7)) * TT + tn) * IND + (i0 & 127)];
            if (i1 < ROWS * IND)
                xr1 = x[((size_t)(b0 + (i1 >> 7)) * TT + tn) * IND + (i1 & 127)];
        }
        __syncthreads();

        // ============ (e) layer-1 partials ============
        if (act1) {
            const ulonglong2* Wp =
                (const ulonglong2*)(g_W1[mat] + (size_t)kb1 * S1 + jg1 * 4);
            unsigned long long aA0 = 0, aB0 = 0, aA1 = 0, aB1 = 0;
            unsigned long long aA2 = 0, aB2 = 0, aA3 = 0, aB3 = 0;
            const float* ab = xh1d + kb1 * 8;
            #pragma unroll 6
            for (int k = kb1; k < ke1; ++k) {
                ulonglong2 w = *Wp; Wp += (S1 / 4);
                ulonglong2 d01 = *(const ulonglong2*)(ab);
                ulonglong2 d23 = *(const ulonglong2*)(ab + 4);
                ab += 8;
                aA0 = fma2(w.x, d01.x, aA0); aB0 = fma2(w.y, d01.x, aB0);
                aA1 = fma2(w.x, d01.y, aA1); aB1 = fma2(w.y, d01.y, aB1);
                aA2 = fma2(w.x, d23.x, aA2); aB2 = fma2(w.y, d23.x, aB2);
                aA3 = fma2(w.x, d23.y, aA3); aB3 = fma2(w.y, d23.y, aB3);
            }
            float* P = part + (size_t)((kc1 * 3 + mat) * 4) * 128 + jg1 * 4;
            *(ulonglong2*)(P)       = make_ulonglong2(aA0, aB0);
            *(ulonglong2*)(P + 128) = make_ulonglong2(aA1, aB1);
            *(ulonglong2*)(P + 256) = make_ulonglong2(aA2, aB2);
            *(ulonglong2*)(P + 384) = make_ulonglong2(aA3, aB3);
        }
        __syncthreads();

        // ============ (g) combine layer-1 ============
        if (jj < NC) {
            float a1 = 0.f, a2 = 0.f, ac = 0.f;
            #pragma unroll
            for (int c = 0; c < 6; ++c) {
                a1 += part[((c * 3 + 0) * 4 + rsel) * 128 + jj];
                a2 += part[((c * 3 + 1) * 4 + rsel) * 128 + jj];
                ac += part[((c * 3 + 2) * 4 + rsel) * 128 + jj];
            }
            float h = cfc_mix(a1, a2, ac, rb1_1, rb2_1, rbc_1);
            *(unsigned long long*)&xh1d[(NI + jj) * 8 + rsel * 2] = pack2(h, h);
            xh2[jj * 4 + rsel] = h;
            if (mat == 0) {
                float c1 = 0.f, c2 = 0.f, cc = 0.f;
                #pragma unroll
                for (int c = 0; c < 6; ++c) {
                    c1 += part[((c * 3 + 0) * 4 + 3) * 128 + jj];
                    c2 += part[((c * 3 + 1) * 4 + 3) * 128 + jj];
                    cc += part[((c * 3 + 2) * 4 + 3) * 128 + jj];
                }
                float h3 = cfc_mix(c1, c2, cc, rb1_1, rb2_1, rbc_1);
                *(unsigned long long*)&xh1d[(NI + jj) * 8 + 6] = pack2(h3, h3);
                xh2[jj * 4 + 3] = h3;
            }
        }
        __syncthreads();

        // ============ (i) layer-2 partials ============
        {
            int j2 = jj & 7, kc2 = jj >> 3;
            int kb = kc2 * 6;
            int ke = kb + 6; if (ke > CAT2) ke = CAT2; if (kb > CAT2) kb = CAT2;
            unsigned long long p01 = 0, p23 = 0;
            const float* W = sw2 + mat * (CAT2 * S2) + j2;
            for (int k = kb; k < ke; ++k) {
                float w = W[k * 8];
                unsigned long long ww = pack2(w, w);
                ulonglong2 u = *(const ulonglong2*)&xh2[k * 4];
                p01 = fma2(ww, u.x, p01);
                p23 = fma2(ww, u.y, p23);
            }
            *(ulonglong2*)&part2[(mat * 160 + jj) * 4] = make_ulonglong2(p01, p23);
        }
        __syncthreads();

        // ============ (k) combine layer-2 (8 threads) ============
        if (mat == 0 && jj < NM) {
            unsigned long long s0a = 0, s0b = 0, s1a = 0, s1b = 0, s2a = 0, s2b = 0;
            #pragma unroll 4
            for (int kc = 0; kc < 20; ++kc) {
                int p = (kc * 8 + jj) * 4;
                ulonglong2 u0 = *(const ulonglong2*)&part2[p];
                ulonglong2 u1 = *(const ulonglong2*)&part2[640 + p];
                ulonglong2 u2 = *(const ulonglong2*)&part2[1280 + p];
                s0a = add2(s0a, u0.x); s0b = add2(s0b, u0.y);
                s1a = add2(s1a, u1.x); s1b = add2(s1b, u1.y);
                s2a = add2(s2a, u2.x); s2b = add2(s2b, u2.y);
            }
            float a1[4], a2[4], ac[4];
            unpack2(s0a, a1[0], a1[1]); unpack2(s0b, a1[2], a1[3]);
            unpack2(s1a, a2[0], a2[1]); unpack2(s1b, a2[2], a2[3]);
            unpack2(s2a, ac[0], ac[1]); unpack2(s2b, ac[2], ac[3]);
            #pragma unroll
            for (int r = 0; r < 4; ++r) {
                float h = cfc_mix(a1[r], a2[r], ac[r], rb1_2, rb2_2, rbc_2);
                xh2[(NC + jj) * 4 + r] = h;
                out[((size_t)(b0 + r) * TT + t) * NM + jj] = tanhf(h);
            }
        }
        // no barrier: next write to part2/xh2[NC+..] is ≥4 barriers away
    }

    __syncthreads();
    if (write_h) {
        size_t base = (size_t)BB * TT * NM;
        for (int pass = 0; pass < 2; ++pass) {
            int rr = (pass == 0) ? rsel : 3;
            if (pass == 1 && mat != 0) break;
            size_t ro = base + (size_t)(b0 + rr) * 256;
            if (jj < NI) out[ro + jj]           = xh0d[(IND + jj) * 8 + rr * 2];
            if (jj < NC) out[ro + NI + jj]      = xh1d[(NI + jj) * 8 + rr * 2];
            if (jj < NM) out[ro + NI + NC + jj] = xh2[(NC + jj) * 4 + rr];
        }
    }
}

// ---------------------------------------------------------------------------
extern "C" void kernel_launch(void* const* d_in, const int* in_sizes, int n_in,
                              void* d_out, int out_size)
{
    const float *x, *dt;
    const float *w1[3], *b1[3], *w2[3], *b2[3], *wa[3], *ba[3], *wb[3], *bb[3];
    const int   *m[3];

    if (in_sizes[0] == BB * TT * IND) {
        x  = (const float*)d_in[0];
        dt = (const float*)d_in[1];
        for (int l = 0; l < 3; l++) {
            int base = 2 + 9 * l;
            w1[l] = (const float*)d_in[base + 0];
            b1[l] = (const float*)d_in[base + 1];
            w2[l] = (const float*)d_in[base + 2];
            b2[l] = (const float*)d_in[base + 3];
            wa[l] = (const float*)d_in[base + 4];
            ba[l] = (const float*)d_in[base + 5];
            wb[l] = (const float*)d_in[base + 6];
            bb[l] = (const float*)d_in[base + 7];
            m[l]  = (const int*)  d_in[base + 8];
        }
    } else {
        for (int l = 0; l < 3; l++) {
            int base = 9 * l;
            w1[l] = (const float*)d_in[base + 0];
            w2[l] = (const float*)d_in[base + 1];
            wa[l] = (const float*)d_in[base + 2];
            wb[l] = (const float*)d_in[base + 3];
            b1[l] = (const float*)d_in[base + 4];
            b2[l] = (const float*)d_in[base + 5];
            ba[l] = (const float*)d_in[base + 6];
            bb[l] = (const float*)d_in[base + 7];
            m[l]  = (const int*)  d_in[base + 8];
        }
        x  = (const float*)d_in[27];
        dt = (const float*)d_in[28];
    }

    cfc_precompute_kernel<<<148, 256>>>(
        w1[0], w2[0], wa[0], wb[0], ba[0], bb[0], m[0],
        w1[1], w2[1], wa[1], wb[1], ba[1], bb[1], m[1],
        w1[2], w2[2], wa[2], wb[2], ba[2], bb[2], m[2],
        dt);

    cudaFuncSetAttribute(cfc_main_kernel,
                         cudaFuncAttributeMaxDynamicSharedMemorySize, SMEM_BYTES);

    int write_h = (out_size >= BB * TT * NM + BB * 256) ? 1 : 0;
    cfc_main_kernel<<<BB / ROWS, NTH, SMEM_BYTES>>>(
        x, b1[0], b2[0], b1[1], b2[1], b1[2], b2[2],
        (float*)d_out, write_h);
}

// round 6
// speedup vs baseline: 1.1975x; 1.1975x over previous
#include <cuda_runtime.h>
#include <math.h>

// Problem constants
#define BB   256
#define TT   512
#define IND  128
#define NI   149
#define NC   99
#define NM   8
#define CAT0 (IND + NI)   // 277
#define CAT1 (NI + NC)    // 248
#define CAT2 (NC + NM)    // 107
#define S0   160          // padded j-stride layer0
#define S1   128          // padded j-stride layer1
#define S2   8
#define K0P  280          // padded k layer0 (8 chunks x 35)
#define K1P  252          // padded k layer1 (12 chunks x 21)
#define ROWS 4
#define NTH  480

// SMEM layout (floats)
#define OFF_XH0   0                  // 280*8 = 2240 (dup pairs per row)
#define OFF_XH1   2240               // 252*8 = 2016
#define OFF_XH2   4256               // 110*4 = 440 (+pad)
#define OFF_PART  4704               // 7680
#define OFF_PART2 12384              // 1920
#define OFF_SW2   14304              // 3*107*8 = 2568
#define OFF_MBAR  16872              // 4 mbarriers (8 floats)
#define SMEM_FLOATS 16880
#define SMEM_BYTES  (SMEM_FLOATS * 4)

// mbarrier float-offsets
#define MB_RD0  (OFF_MBAR + 0)
#define MB_RD1  (OFF_MBAR + 2)
#define MB_FL0  (OFF_MBAR + 4)
#define MB_FL1  (OFF_MBAR + 6)

// Precomputed fused/masked/transposed weights (padded j AND k zeroed)
__device__ float g_W0[3][K0P * S0];
__device__ float g_W1[3][K1P * S1];
__device__ float g_W2[3][CAT2 * S2];
__device__ float g_bc[NI + NC + NM];

// ---------------------------------------------------------------------------
__global__ void cfc_precompute_kernel(
    const float* __restrict__ w1_0, const float* __restrict__ w2_0,
    const float* __restrict__ wa_0, const float* __restrict__ wb_0,
    const float* __restrict__ ba_0, const float* __restrict__ bb_0,
    const int*   __restrict__ m0,
    const float* __restrict__ w1_1, const float* __restrict__ w2_1,
    const float* __restrict__ wa_1, const float* __restrict__ wb_1,
    const float* __restrict__ ba_1, const float* __restrict__ bb_1,
    const int*   __restrict__ m1,
    const float* __restrict__ w1_2, const float* __restrict__ w2_2,
    const float* __restrict__ wa_2, const float* __restrict__ wb_2,
    const float* __restrict__ ba_2, const float* __restrict__ bb_2,
    const int*   __restrict__ m2,
    const float* __restrict__ dt)
{
    const float ts = dt[0];
    const int idx    = blockIdx.x * blockDim.x + threadIdx.x;
    const int stride = gridDim.x * blockDim.x;

    for (int i = idx; i < K0P * S0; i += stride) {
        int k = i / S0, j = i - k * S0;
        float v1 = 0.f, v2 = 0.f, vc = 0.f;
        if (j < NI && k < CAT0) {
            int src = j * CAT0 + k;
            float mm = (float)m0[src];
            v1 = w1_0[src] * mm;
            v2 = w2_0[src] * mm;
            vc = ts * wa_0[src] + wb_0[src];
        }
        g_W0[0][i] = v1; g_W0[1][i] = v2; g_W0[2][i] = vc;
    }
    for (int i = idx; i < K1P * S1; i += stride) {
        int k = i / S1, j = i - k * S1;
        float v1 = 0.f, v2 = 0.f, vc = 0.f;
        if (j < NC && k < CAT1) {
            int src = j * CAT1 + k;
            float mm = (float)m1[src];
            v1 = w1_1[src] * mm;
            v2 = w2_1[src] * mm;
            vc = ts * wa_1[src] + wb_1[src];
        }
        g_W1[0][i] = v1; g_W1[1][i] = v2; g_W1[2][i] = vc;
    }
    for (int i = idx; i < CAT2 * S2; i += stride) {
        int k = i / S2, j = i - k * S2;
        int src = j * CAT2 + k;
        float mm = (float)m2[src];
        g_W2[0][i] = w1_2[src] * mm;
        g_W2[1][i] = w2_2[src] * mm;
        g_W2[2][i] = ts * wa_2[src] + wb_2[src];
    }
    for (int j = idx; j < NI; j += stride) g_bc[j]           = ts * ba_0[j] + bb_0[j];
    for (int j = idx; j < NC; j += stride) g_bc[NI + j]      = ts * ba_1[j] + bb_1[j];
    for (int j = idx; j < NM; j += stride) g_bc[NI + NC + j] = ts * ba_2[j] + bb_2[j];
}

// ---------------------------------------------------------------------------
// Packed fp32x2 + cluster helpers
// ---------------------------------------------------------------------------
__device__ __forceinline__ unsigned long long pack2(float a, float b) {
    unsigned long long r;
    asm("mov.b64 %0, {%1, %2};" : "=l"(r) : "f"(a), "f"(b));
    return r;
}
__device__ __forceinline__ void unpack2(unsigned long long v, float& a, float& b) {
    asm("mov.b64 {%0, %1}, %2;" : "=f"(a), "=f"(b) : "l"(v));
}
__device__ __forceinline__ unsigned long long fma2(unsigned long long a,
                                                   unsigned long long b,
                                                   unsigned long long c) {
    unsigned long long d;
    asm("fma.rn.f32x2 %0, %1, %2, %3;" : "=l"(d) : "l"(a), "l"(b), "l"(c));
    return d;
}
__device__ __forceinline__ unsigned long long add2(unsigned long long a,
                                                   unsigned long long b) {
    unsigned long long d;
    asm("add.rn.f32x2 %0, %1, %2;" : "=l"(d) : "l"(a), "l"(b));
    return d;
}
__device__ __forceinline__ float sigmoidf_(float z) { return 1.0f / (1.0f + expf(-z)); }
__device__ __forceinline__ float cfc_mix(float a1, float a2, float ac,
                                         float b1, float b2, float bc) {
    float ff1 = tanhf(a1 + b1);
    float ff2 = tanhf(a2 + b2);
    float ti  = sigmoidf_(ac + bc);
    return ff1 + ti * (ff2 - ff1);
}

__device__ __forceinline__ unsigned smem_u32(const void* p) {
    unsigned a;
    asm("{ .reg .u64 t; cvta.to.shared.u64 t, %1; cvt.u32.u64 %0, t; }"
        : "=r"(a) : "l"(p));
    return a;
}
__device__ __forceinline__ void mbar_init(unsigned addr, unsigned count) {
    asm volatile("mbarrier.init.shared.b64 [%0], %1;" :: "r"(addr), "r"(count) : "memory");
}
__device__ __forceinline__ void mbar_wait(unsigned addr, unsigned parity) {
    unsigned done = 0;
    do {
        asm volatile(
            "{\n\t.reg .pred P;\n\t"
            "mbarrier.try_wait.parity.acquire.cluster.shared::cta.b64 P, [%1], %2, 0x989680;\n\t"
            "selp.b32 %0, 1, 0, P;\n\t}"
            : "=r"(done) : "r"(addr), "r"(parity) : "memory");
    } while (!done);
}
__device__ __forceinline__ void mbar_arrive_peer(unsigned addr, unsigned peer) {
    asm volatile(
        "{\n\t.reg .b32 ra;\n\t"
        "mapa.shared::cluster.u32 ra, %0, %1;\n\t"
        "mbarrier.arrive.release.cluster.shared::cluster.b64 _, [ra];\n\t}"
        :: "r"(addr), "r"(peer) : "memory");
}
__device__ __forceinline__ void st_peer_u64(unsigned addr, unsigned peer,
                                            unsigned long long v) {
    asm volatile(
        "{\n\t.reg .b32 ra;\n\t"
        "mapa.shared::cluster.u32 ra, %0, %1;\n\t"
        "st.shared::cluster.u64 [ra], %2;\n\t}"
        :: "r"(addr), "r"(peer), "l"(v) : "memory");
}
__device__ __forceinline__ void st_peer_u32(unsigned addr, unsigned peer, float v) {
    asm volatile(
        "{\n\t.reg .b32 ra;\n\t"
        "mapa.shared::cluster.u32 ra, %0, %1;\n\t"
        "st.shared::cluster.f32 [ra], %2;\n\t}"
        :: "r"(addr), "r"(peer), "f"(v) : "memory");
}

// ---------------------------------------------------------------------------
// Main kernel: 128 CTAs in 64 clusters of 2. Cluster owns 4 batch rows; the
// two CTAs split the j (output-neuron) dimension; activations exchanged via
// DSMEM push + mbarrier handshakes.
// ---------------------------------------------------------------------------
__global__ __launch_bounds__(NTH, 1) __cluster_dims__(2, 1, 1)
void cfc_main_kernel(
    const float* __restrict__ x,
    const float* __restrict__ b1_0, const float* __restrict__ b2_0,
    const float* __restrict__ b1_1, const float* __restrict__ b2_1,
    const float* __restrict__ b1_2, const float* __restrict__ b2_2,
    float* __restrict__ out, int write_h)
{
    extern __shared__ float sm[];
    float* xh0d  = sm + OFF_XH0;
    float* xh1d  = sm + OFF_XH1;
    float* xh2   = sm + OFF_XH2;
    float* part  = sm + OFF_PART;
    float* part2 = sm + OFF_PART2;
    float* sw2   = sm + OFF_SW2;

    const int tid = threadIdx.x;
    unsigned rank;
    asm("mov.u32 %0, %%cluster_ctarank;" : "=r"(rank));
    const unsigned peer = rank ^ 1u;
    const int b0  = (blockIdx.x >> 1) * ROWS;

    const int nj0 = rank ? 73 : 76;
    const int jb0 = rank ? 76 : 0;
    const int nj1 = rank ? 47 : 52;
    const int jb1 = rank ? 52 : 0;

    const unsigned sbase = smem_u32(sm);
    const unsigned a_rd0 = sbase + MB_RD0 * 4;
    const unsigned a_rd1 = sbase + MB_RD1 * 4;
    const unsigned a_fl0 = sbase + MB_FL0 * 4;
    const unsigned a_fl1 = sbase + MB_FL1 * 4;

    const int mat = tid / 160;
    const int rem = tid - mat * 160;
    const int jj  = rem;
    const int rsel = (mat == 0) ? 0 : mat;

    // decomposition: L0 = 20 j-groups x 8 k-chunks(35); L1 = 13 j-groups x 12 k-chunks(21)
    const int jg0 = rem % 20, kc0 = rem / 20;
    const int kb0 = kc0 * 35;
    const int jg1 = rem % 13, kc1 = rem / 13;
    const int kb1 = kc1 * 21;
    const bool act1 = (kc1 < 12);

    // ---- prologue ----
    for (int i = tid; i < 2240; i += NTH) xh0d[i] = 0.f;
    for (int i = tid; i < 2016; i += NTH) xh1d[i] = 0.f;
    for (int i = tid; i < 448;  i += NTH) xh2[i]  = 0.f;
    for (int i = tid; i < 3 * CAT2 * S2; i += NTH) sw2[i] = ((const float*)g_W2)[i];

    if (tid == 0) {
        mbar_init(a_rd0, 1);
        mbar_init(a_rd1, 1);
        mbar_init(a_fl0, rank ? 228 : 219);   // expected = peer's writer count (3*nj0_peer)
        mbar_init(a_fl1, rank ? 156 : 141);   // 3*nj1_peer
    }

    float rb1_0 = 0.f, rb2_0 = 0.f, rbc_0 = 0.f;
    float rb1_1 = 0.f, rb2_1 = 0.f, rbc_1 = 0.f;
    float rb1_2 = 0.f, rb2_2 = 0.f, rbc_2 = 0.f;
    if (jj < nj0) { rb1_0 = b1_0[jb0 + jj]; rb2_0 = b2_0[jb0 + jj]; rbc_0 = g_bc[jb0 + jj]; }
    if (jj < nj1) { rb1_1 = b1_1[jb1 + jj]; rb2_1 = b2_1[jb1 + jj]; rbc_1 = g_bc[NI + jb1 + jj]; }
    if (jj < NM)  { rb1_2 = b1_2[jj]; rb2_2 = b2_2[jj]; rbc_2 = g_bc[NI + NC + jj]; }

    // stage x_0 (duplicated pairs), prefetch x_1
    const int i0 = tid, i1 = tid + NTH;
    for (int i = tid; i < ROWS * IND; i += NTH) {
        int r = i >> 7, k = i & 127;
        float v = x[((size_t)(b0 + r) * TT + 0) * IND + k];
        *(unsigned long long*)&xh0d[k * 8 + r * 2] = pack2(v, v);
    }
    float xr0 = x[((size_t)(b0 + (i0 >> 7)) * TT + 1) * IND + (i0 & 127)];
    float xr1 = 0.f;
    if (i1 < ROWS * IND)
        xr1 = x[((size_t)(b0 + (i1 >> 7)) * TT + 1) * IND + (i1 & 127)];

    __syncthreads();
    asm volatile("barrier.cluster.arrive.aligned;" ::: "memory");
    asm volatile("barrier.cluster.wait.aligned;" ::: "memory");

    unsigned ph0 = 0, ph1 = 0, prd0 = 0, prd1 = 0;

    for (int t = 0; t < TT; ++t) {
        // ============ (a) layer-0 partials: 35 k per thread, prefetched ============
        {
            const ulonglong2* Wp =
                (const ulonglong2*)(g_W0[mat] + (size_t)kb0 * S0 + jb0 + jg0 * 4);
            const float* ab = xh0d + kb0 * 8;
            unsigned long long aA0 = 0, aB0 = 0, aA1 = 0, aB1 = 0;
            unsigned long long aA2 = 0, aB2 = 0, aA3 = 0, aB3 = 0;
            ulonglong2 wreg[5];
            #pragma unroll
            for (int i = 0; i < 5; ++i) wreg[i] = Wp[i * (S0 / 4)];
            Wp += 5 * (S0 / 4);
            #pragma unroll
            for (int b = 0; b < 7; ++b) {
                ulonglong2 wnxt[5];
                if (b + 1 < 7) {
                    #pragma unroll
                    for (int i = 0; i < 5; ++i) wnxt[i] = Wp[i * (S0 / 4)];
                    Wp += 5 * (S0 / 4);
                }
                #pragma unroll
                for (int i = 0; i < 5; ++i) {
                    ulonglong2 d01 = *(const ulonglong2*)(ab);
                    ulonglong2 d23 = *(const ulonglong2*)(ab + 4);
                    ab += 8;
                    aA0 = fma2(wreg[i].x, d01.x, aA0); aB0 = fma2(wreg[i].y, d01.x, aB0);
                    aA1 = fma2(wreg[i].x, d01.y, aA1); aB1 = fma2(wreg[i].y, d01.y, aB1);
                    aA2 = fma2(wreg[i].x, d23.x, aA2); aB2 = fma2(wreg[i].y, d23.x, aB2);
                    aA3 = fma2(wreg[i].x, d23.y, aA3); aB3 = fma2(wreg[i].y, d23.y, aB3);
                }
                if (b + 1 < 7) {
                    #pragma unroll
                    for (int i = 0; i < 5; ++i) wreg[i] = wnxt[i];
                }
            }
            float* P = part + (size_t)((kc0 * 3 + mat) * 4) * 80 + jg0 * 4;
            *(ulonglong2*)(P)       = make_ulonglong2(aA0, aB0);
            *(ulonglong2*)(P + 80)  = make_ulonglong2(aA1, aB1);
            *(ulonglong2*)(P + 160) = make_ulonglong2(aA2, aB2);
            *(ulonglong2*)(P + 240) = make_ulonglong2(aA3, aB3);
        }
        __syncthreads();
        if (tid == 0) mbar_arrive_peer(a_rd0, peer);   // "we finished reading xh0"

        // ============ (c) combine layer-0 (local j half) + exchange ============
        if (jj < nj0) {
            float a1 = 0.f, a2 = 0.f, ac = 0.f;
            #pragma unroll
            for (int c = 0; c < 8; ++c) {
                a1 += part[((c * 3 + 0) * 4 + rsel) * 80 + jj];
                a2 += part[((c * 3 + 1) * 4 + rsel) * 80 + jj];
                ac += part[((c * 3 + 2) * 4 + rsel) * 80 + jj];
            }
            float h = cfc_mix(a1, a2, ac, rb1_0, rb2_0, rbc_0);
            unsigned long long hh = pack2(h, h);
            const int jg = jb0 + jj;
            const int o0 = (IND + jg) * 8 + rsel * 2;
            const int o1 = jg * 8 + rsel * 2;
            *(unsigned long long*)&xh0d[o0] = hh;
            *(unsigned long long*)&xh1d[o1] = hh;
            float h3 = 0.f; unsigned long long hh3 = 0;
            if (mat == 0) {
                float c1 = 0.f, c2 = 0.f, cc = 0.f;
                #pragma unroll
                for (int c = 0; c < 8; ++c) {
                    c1 += part[((c * 3 + 0) * 4 + 3) * 80 + jj];
                    c2 += part[((c * 3 + 1) * 4 + 3) * 80 + jj];
                    cc += part[((c * 3 + 2) * 4 + 3) * 80 + jj];
                }
                h3 = cfc_mix(c1, c2, cc, rb1_0, rb2_0, rbc_0);
                hh3 = pack2(h3, h3);
                *(unsigned long long*)&xh0d[o0 + 6 - rsel * 2] = hh3;  // row3 slot
                *(unsigned long long*)&xh1d[o1 + 6 - rsel * 2] = hh3;
            }
            mbar_wait(a_rd0, prd0);                    // peer done reading its xh0
            st_peer_u64(sbase + (OFF_XH0 + o0) * 4, peer, hh);
            st_peer_u64(sbase + (OFF_XH1 + o1) * 4, peer, hh);
            if (mat == 0) {
                st_peer_u64(sbase + (OFF_XH0 + o0 + 6) * 4, peer, hh3);
                st_peer_u64(sbase + (OFF_XH1 + o1 + 6) * 4, peer, hh3);
            }
            mbar_arrive_peer(a_fl0, peer);
        }
        {   // x restage (local only; both CTAs stage full x)
            *(unsigned long long*)&xh0d[(i0 & 127) * 8 + (i0 >> 7) * 2] = pack2(xr0, xr0);
            if (i1 < ROWS * IND)
                *(unsigned long long*)&xh0d[(i1 & 127) * 8 + (i1 >> 7) * 2] = pack2(xr1, xr1);
            int tn = t + 2; if (tn > TT - 1) tn = TT - 1;
            xr0 = x[((size_t)(b0 + (i0 >> 7)) * TT + tn) * IND + (i0 & 127)];
            if (i1 < ROWS * IND)
                xr1 = x[((size_t)(b0 + (i1 >> 7)) * TT + tn) * IND + (i1 & 127)];
        }
        __syncthreads();
        mbar_wait(a_fl0, ph0);                         // peer's h0 half arrived
        ph0 ^= 1; prd0 ^= 1;

        // ============ (e) layer-1 partials: 21 k per thread, prefetched ============
        if (act1) {
            const ulonglong2* Wp =
                (const ulonglong2*)(g_W1[mat] + (size_t)kb1 * S1 + jb1 + jg1 * 4);
            const float* ab = xh1d + kb1 * 8;
            unsigned long long aA0 = 0, aB0 = 0, aA1 = 0, aB1 = 0;
            unsigned long long aA2 = 0, aB2 = 0, aA3 = 0, aB3 = 0;
            ulonglong2 wreg[7];
            #pragma unroll
            for (int i = 0; i < 7; ++i) wreg[i] = Wp[i * (S1 / 4)];
            Wp += 7 * (S1 / 4);
            #pragma unroll
            for (int b = 0; b < 3; ++b) {
                ulonglong2 wnxt[7];
                if (b + 1 < 3) {
                    #pragma unroll
                    for (int i = 0; i < 7; ++i) wnxt[i] = Wp[i * (S1 / 4)];
                    Wp += 7 * (S1 / 4);
                }
                #pragma unroll
                for (int i = 0; i < 7; ++i) {
                    ulonglong2 d01 = *(const ulonglong2*)(ab);
                    ulonglong2 d23 = *(const ulonglong2*)(ab + 4);
                    ab += 8;
                    aA0 = fma2(wreg[i].x, d01.x, aA0); aB0 = fma2(wreg[i].y, d01.x, aB0);
                    aA1 = fma2(wreg[i].x, d01.y, aA1); aB1 = fma2(wreg[i].y, d01.y, aB1);
                    aA2 = fma2(wreg[i].x, d23.x, aA2); aB2 = fma2(wreg[i].y, d23.x, aB2);
                    aA3 = fma2(wreg[i].x, d23.y, aA3); aB3 = fma2(wreg[i].y, d23.y, aB3);
                }
                if (b + 1 < 3) {
                    #pragma unroll
                    for (int i = 0; i < 7; ++i) wreg[i] = wnxt[i];
                }
            }
            float* P = part + (size_t)((kc1 * 3 + mat) * 4) * 52 + jg1 * 4;
            *(ulonglong2*)(P)       = make_ulonglong2(aA0, aB0);
            *(ulonglong2*)(P + 52)  = make_ulonglong2(aA1, aB1);
            *(ulonglong2*)(P + 104) = make_ulonglong2(aA2, aB2);
            *(ulonglong2*)(P + 156) = make_ulonglong2(aA3, aB3);
        }
        __syncthreads();
        if (tid == 0) mbar_arrive_peer(a_rd1, peer);   // "we finished reading xh1"

        // ============ (g) combine layer-1 (local j half) + exchange ============
        if (jj < nj1) {
            float a1 = 0.f, a2 = 0.f, ac = 0.f;
            #pragma unroll
            for (int c = 0; c < 12; ++c) {
                a1 += part[((c * 3 + 0) * 4 + rsel) * 52 + jj];
                a2 += part[((c * 3 + 1) * 4 + rsel) * 52 + jj];
                ac += part[((c * 3 + 2) * 4 + rsel) * 52 + jj];
            }
            float h = cfc_mix(a1, a2, ac, rb1_1, rb2_1, rbc_1);
            unsigned long long hh = pack2(h, h);
            const int jg = jb1 + jj;
            const int o1 = (NI + jg) * 8 + rsel * 2;
            const int o2 = jg * 4 + rsel;
            *(unsigned long long*)&xh1d[o1] = hh;
            xh2[o2] = h;
            float h3 = 0.f; unsigned long long hh3 = 0;
            if (mat == 0) {
                float c1 = 0.f, c2 = 0.f, cc = 0.f;
                #pragma unroll
                for (int c = 0; c < 12; ++c) {
                    c1 += part[((c * 3 + 0) * 4 + 3) * 52 + jj];
                    c2 += part[((c * 3 + 1) * 4 + 3) * 52 + jj];
                    cc += part[((c * 3 + 2) * 4 + 3) * 52 + jj];
                }
                h3 = cfc_mix(c1, c2, cc, rb1_1, rb2_1, rbc_1);
                hh3 = pack2(h3, h3);
                *(unsigned long long*)&xh1d[(NI + jg) * 8 + 6] = hh3;
                xh2[jg * 4 + 3] = h3;
            }
            mbar_wait(a_rd1, prd1);                    // peer done reading its xh1
            st_peer_u64(sbase + (OFF_XH1 + o1) * 4, peer, hh);
            st_peer_u32(sbase + (OFF_XH2 + o2) * 4, peer, h);
            if (mat == 0) {
                st_peer_u64(sbase + (OFF_XH1 + (NI + jg) * 8 + 6) * 4, peer, hh3);
                st_peer_u32(sbase + (OFF_XH2 + jg * 4 + 3) * 4, peer, h3);
            }
            mbar_arrive_peer(a_fl1, peer);
        }
        __syncthreads();
        mbar_wait(a_fl1, ph1);                         // peer's h1 half arrived
        ph1 ^= 1; prd1 ^= 1;

        // ============ (i) layer-2 partials (redundant on both ranks) ============
        {
            int j2 = jj & 7, kc2 = jj >> 3;
            int kb = kc2 * 6;
            int ke = kb + 6; if (ke > CAT2) ke = CAT2; if (kb > CAT2) kb = CAT2;
            unsigned long long p01 = 0, p23 = 0;
            const float* W = sw2 + mat * (CAT2 * S2) + j2;
            for (int k = kb; k < ke; ++k) {
                float w = W[k * 8];
                unsigned long long ww = pack2(w, w);
                ulonglong2 u = *(const ulonglong2*)&xh2[k * 4];
                p01 = fma2(ww, u.x, p01);
                p23 = fma2(ww, u.y, p23);
            }
            *(ulonglong2*)&part2[(mat * 160 + jj) * 4] = make_ulonglong2(p01, p23);
        }
        __syncthreads();

        // ============ (k) combine layer-2 (both ranks; rank0 writes y) ============
        if (mat == 0 && jj < NM) {
            unsigned long long s0a = 0, s0b = 0, s1a = 0, s1b = 0, s2a = 0, s2b = 0;
            #pragma unroll 4
            for (int kc = 0; kc < 20; ++kc) {
                int p = (kc * 8 + jj) * 4;
                ulonglong2 u0 = *(const ulonglong2*)&part2[p];
                ulonglong2 u1 = *(const ulonglong2*)&part2[640 + p];
                ulonglong2 u2 = *(const ulonglong2*)&part2[1280 + p];
                s0a = add2(s0a, u0.x); s0b = add2(s0b, u0.y);
                s1a = add2(s1a, u1.x); s1b = add2(s1b, u1.y);
                s2a = add2(s2a, u2.x); s2b = add2(s2b, u2.y);
            }
            float a1[4], a2[4], ac[4];
            unpack2(s0a, a1[0], a1[1]); unpack2(s0b, a1[2], a1[3]);
            unpack2(s1a, a2[0], a2[1]); unpack2(s1b, a2[2], a2[3]);
            unpack2(s2a, ac[0], ac[1]); unpack2(s2b, ac[2], ac[3]);
            #pragma unroll
            for (int r = 0; r < 4; ++r) {
                float h = cfc_mix(a1[r], a2[r], ac[r], rb1_2, rb2_2, rbc_2);
                xh2[(NC + jj) * 4 + r] = h;
                if (rank == 0)
                    out[((size_t)(b0 + r) * TT + t) * NM + jj] = tanhf(h);
            }
        }
        // no barrier: next conflicting access to part2/xh2[NC+..] is several
        // barriers away (end-(a), (c) sync, fl0 wait, end-(e), fl1 wait).
    }

    __syncthreads();
    if (write_h && rank == 0) {
        size_t base = (size_t)BB * TT * NM;
        for (int pass = 0; pass < 2; ++pass) {
            int rr = (pass == 0) ? rsel : 3;
            if (pass == 1 && mat != 0) break;
            size_t ro = base + (size_t)(b0 + rr) * 256;
            if (jj < NI) out[ro + jj]           = xh0d[(IND + jj) * 8 + rr * 2];
            if (jj < NC) out[ro + NI + jj]      = xh1d[(NI + jj) * 8 + rr * 2];
            if (jj < NM) out[ro + NI + NC + jj] = xh2[(NC + jj) * 4 + rr];
        }
    }
    asm volatile("barrier.cluster.arrive.aligned;" ::: "memory");
    asm volatile("barrier.cluster.wait.aligned;" ::: "memory");
}

// ---------------------------------------------------------------------------
extern "C" void kernel_launch(void* const* d_in, const int* in_sizes, int n_in,
                              void* d_out, int out_size)
{
    const float *x, *dt;
    const float *w1[3], *b1[3], *w2[3], *b2[3], *wa[3], *ba[3], *wb[3], *bb[3];
    const int   *m[3];

    if (in_sizes[0] == BB * TT * IND) {
        x  = (const float*)d_in[0];
        dt = (const float*)d_in[1];
        for (int l = 0; l < 3; l++) {
            int base = 2 + 9 * l;
            w1[l] = (const float*)d_in[base + 0];
            b1[l] = (const float*)d_in[base + 1];
            w2[l] = (const float*)d_in[base + 2];
            b2[l] = (const float*)d_in[base + 3];
            wa[l] = (const float*)d_in[base + 4];
            ba[l] = (const float*)d_in[base + 5];
            wb[l] = (const float*)d_in[base + 6];
            bb[l] = (const float*)d_in[base + 7];
            m[l]  = (const int*)  d_in[base + 8];
        }
    } else {
        for (int l = 0; l < 3; l++) {
            int base = 9 * l;
            w1[l] = (const float*)d_in[base + 0];
            w2[l] = (const float*)d_in[base + 1];
            wa[l] = (const float*)d_in[base + 2];
            wb[l] = (const float*)d_in[base + 3];
            b1[l] = (const float*)d_in[base + 4];
            b2[l] = (const float*)d_in[base + 5];
            ba[l] = (const float*)d_in[base + 6];
            bb[l] = (const float*)d_in[base + 7];
            m[l]  = (const int*)  d_in[base + 8];
        }
        x  = (const float*)d_in[27];
        dt = (const float*)d_in[28];
    }

    cfc_precompute_kernel<<<148, 256>>>(
        w1[0], w2[0], wa[0], wb[0], ba[0], bb[0], m[0],
        w1[1], w2[1], wa[1], wb[1], ba[1], bb[1], m[1],
        w1[2], w2[2], wa[2], wb[2], ba[2], bb[2], m[2],
        dt);

    cudaFuncSetAttribute(cfc_main_kernel,
                         cudaFuncAttributeMaxDynamicSharedMemorySize, SMEM_BYTES);

    int write_h = (out_size >= BB * TT * NM + BB * 256) ? 1 : 0;
    cfc_main_kernel<<<(BB / ROWS) * 2, NTH, SMEM_BYTES>>>(
        x, b1[0], b2[0], b1[1], b2[1], b1[2], b2[2],
        (float*)d_out, write_h);
}

// round 7
// speedup vs baseline: 1.2081x; 1.0088x over previous
#include <cuda_runtime.h>
#include <math.h>

// Problem constants
#define BB   256
#define TT   512
#define IND  128
#define NI   149
#define NC   99
#define NM   8
#define CAT0 (IND + NI)   // 277
#define CAT1 (NI + NC)    // 248
#define CAT2 (NC + NM)    // 107
#define S0   160          // padded j-stride layer0 (global)
#define S1   128          // padded j-stride layer1 (global)
#define S2   8
#define K0P  280          // padded k layer0 (8 chunks x 35)
#define K1P  252          // padded k layer1 (12 chunks x 21)
#define ROWS 4
#define NTH  480
#define SJ1  52           // smem j-stride for layer1 weight cache (j-half)

// SMEM layout (floats)
#define OFF_XH0   0                  // 2240
#define OFF_XH1   2240               // 2016
#define OFF_XH2   4256               // 448
#define OFF_PART  4704               // 7680
#define OFF_PART2 12384              // 1920
#define OFF_SW2   14304              // 2568
#define OFF_SW1   16872              // 3*252*52 = 39312
#define OFF_MBAR  56184              // 4 mbarriers (8 floats)
#define SMEM_FLOATS 56192
#define SMEM_BYTES  (SMEM_FLOATS * 4)   // 224768 B

#define MB_RD0  (OFF_MBAR + 0)
#define MB_RD1  (OFF_MBAR + 2)
#define MB_FL0  (OFF_MBAR + 4)
#define MB_FL1  (OFF_MBAR + 6)

// Precomputed fused/masked/transposed weights (padded j AND k zeroed)
__device__ float g_W0[3][K0P * S0];
__device__ float g_W1[3][K1P * S1];
__device__ float g_W2[3][CAT2 * S2];
__device__ float g_bc[NI + NC + NM];

// ---------------------------------------------------------------------------
__global__ void cfc_precompute_kernel(
    const float* __restrict__ w1_0, const float* __restrict__ w2_0,
    const float* __restrict__ wa_0, const float* __restrict__ wb_0,
    const float* __restrict__ ba_0, const float* __restrict__ bb_0,
    const int*   __restrict__ m0,
    const float* __restrict__ w1_1, const float* __restrict__ w2_1,
    const float* __restrict__ wa_1, const float* __restrict__ wb_1,
    const float* __restrict__ ba_1, const float* __restrict__ bb_1,
    const int*   __restrict__ m1,
    const float* __restrict__ w1_2, const float* __restrict__ w2_2,
    const float* __restrict__ wa_2, const float* __restrict__ wb_2,
    const float* __restrict__ ba_2, const float* __restrict__ bb_2,
    const int*   __restrict__ m2,
    const float* __restrict__ dt)
{
    const float ts = dt[0];
    const int idx    = blockIdx.x * blockDim.x + threadIdx.x;
    const int stride = gridDim.x * blockDim.x;

    for (int i = idx; i < K0P * S0; i += stride) {
        int k = i / S0, j = i - k * S0;
        float v1 = 0.f, v2 = 0.f, vc = 0.f;
        if (j < NI && k < CAT0) {
            int src = j * CAT0 + k;
            float mm = (float)m0[src];
            v1 = w1_0[src] * mm;
            v2 = w2_0[src] * mm;
            vc = ts * wa_0[src] + wb_0[src];
        }
        g_W0[0][i] = v1; g_W0[1][i] = v2; g_W0[2][i] = vc;
    }
    for (int i = idx; i < K1P * S1; i += stride) {
        int k = i / S1, j = i - k * S1;
        float v1 = 0.f, v2 = 0.f, vc = 0.f;
        if (j < NC && k < CAT1) {
            int src = j * CAT1 + k;
            float mm = (float)m1[src];
            v1 = w1_1[src] * mm;
            v2 = w2_1[src] * mm;
            vc = ts * wa_1[src] + wb_1[src];
        }
        g_W1[0][i] = v1; g_W1[1][i] = v2; g_W1[2][i] = vc;
    }
    for (int i = idx; i < CAT2 * S2; i += stride) {
        int k = i / S2, j = i - k * S2;
        int src = j * CAT2 + k;
        float mm = (float)m2[src];
        g_W2[0][i] = w1_2[src] * mm;
        g_W2[1][i] = w2_2[src] * mm;
        g_W2[2][i] = ts * wa_2[src] + wb_2[src];
    }
    for (int j = idx; j < NI; j += stride) g_bc[j]           = ts * ba_0[j] + bb_0[j];
    for (int j = idx; j < NC; j += stride) g_bc[NI + j]      = ts * ba_1[j] + bb_1[j];
    for (int j = idx; j < NM; j += stride) g_bc[NI + NC + j] = ts * ba_2[j] + bb_2[j];
}

// ---------------------------------------------------------------------------
// Packed fp32x2 + cluster helpers
// ---------------------------------------------------------------------------
__device__ __forceinline__ unsigned long long pack2(float a, float b) {
    unsigned long long r;
    asm("mov.b64 %0, {%1, %2};" : "=l"(r) : "f"(a), "f"(b));
    return r;
}
__device__ __forceinline__ void unpack2(unsigned long long v, float& a, float& b) {
    asm("mov.b64 {%0, %1}, %2;" : "=f"(a), "=f"(b) : "l"(v));
}
__device__ __forceinline__ unsigned long long fma2(unsigned long long a,
                                                   unsigned long long b,
                                                   unsigned long long c) {
    unsigned long long d;
    asm("fma.rn.f32x2 %0, %1, %2, %3;" : "=l"(d) : "l"(a), "l"(b), "l"(c));
    return d;
}
__device__ __forceinline__ unsigned long long add2(unsigned long long a,
                                                   unsigned long long b) {
    unsigned long long d;
    asm("add.rn.f32x2 %0, %1, %2;" : "=l"(d) : "l"(a), "l"(b));
    return d;
}
__device__ __forceinline__ float sigmoidf_(float z) { return 1.0f / (1.0f + expf(-z)); }
__device__ __forceinline__ float cfc_mix(float a1, float a2, float ac,
                                         float b1, float b2, float bc) {
    float ff1 = tanhf(a1 + b1);
    float ff2 = tanhf(a2 + b2);
    float ti  = sigmoidf_(ac + bc);
    return ff1 + ti * (ff2 - ff1);
}

__device__ __forceinline__ unsigned smem_u32(const void* p) {
    unsigned a;
    asm("{ .reg .u64 t; cvta.to.shared.u64 t, %1; cvt.u32.u64 %0, t; }"
        : "=r"(a) : "l"(p));
    return a;
}
__device__ __forceinline__ void mbar_init(unsigned addr, unsigned count) {
    asm volatile("mbarrier.init.shared.b64 [%0], %1;" :: "r"(addr), "r"(count) : "memory");
}
__device__ __forceinline__ void mbar_wait(unsigned addr, unsigned parity) {
    unsigned done = 0;
    do {
        asm volatile(
            "{\n\t.reg .pred P;\n\t"
            "mbarrier.try_wait.parity.acquire.cluster.shared::cta.b64 P, [%1], %2, 0x989680;\n\t"
            "selp.b32 %0, 1, 0, P;\n\t}"
            : "=r"(done) : "r"(addr), "r"(parity) : "memory");
    } while (!done);
}
__device__ __forceinline__ void mbar_arrive_peer(unsigned addr, unsigned peer) {
    asm volatile(
        "{\n\t.reg .b32 ra;\n\t"
        "mapa.shared::cluster.u32 ra, %0, %1;\n\t"
        "mbarrier.arrive.release.cluster.shared::cluster.b64 _, [ra];\n\t}"
        :: "r"(addr), "r"(peer) : "memory");
}
// Aggregated publish: all prior stores (any thread, ordered via preceding
// __syncthreads) become cluster-visible before the single release arrive.
__device__ __forceinline__ void fence_arrive_peer(unsigned addr, unsigned peer) {
    asm volatile("fence.acq_rel.cluster;" ::: "memory");
    mbar_arrive_peer(addr, peer);
}
__device__ __forceinline__ void st_peer_u64(unsigned addr, unsigned peer,
                                            unsigned long long v) {
    asm volatile(
        "{\n\t.reg .b32 ra;\n\t"
        "mapa.shared::cluster.u32 ra, %0, %1;\n\t"
        "st.shared::cluster.u64 [ra], %2;\n\t}"
        :: "r"(addr), "r"(peer), "l"(v) : "memory");
}
__device__ __forceinline__ void st_peer_u32(unsigned addr, unsigned peer, float v) {
    asm volatile(
        "{\n\t.reg .b32 ra;\n\t"
        "mapa.shared::cluster.u32 ra, %0, %1;\n\t"
        "st.shared::cluster.f32 [ra], %2;\n\t}"
        :: "r"(addr), "r"(peer), "f"(v) : "memory");
}

// ---------------------------------------------------------------------------
// Main kernel: 128 CTAs in 64 clusters of 2; cluster owns 4 batch rows; the
// two CTAs split the j dimension. Layer-1 weights resident in SMEM.
// ---------------------------------------------------------------------------
__global__ __launch_bounds__(NTH, 1) __cluster_dims__(2, 1, 1)
void cfc_main_kernel(
    const float* __restrict__ x,
    const float* __restrict__ b1_0, const float* __restrict__ b2_0,
    const float* __restrict__ b1_1, const float* __restrict__ b2_1,
    const float* __restrict__ b1_2, const float* __restrict__ b2_2,
    float* __restrict__ out, int write_h)
{
    extern __shared__ float sm[];
    float* xh0d  = sm + OFF_XH0;
    float* xh1d  = sm + OFF_XH1;
    float* xh2   = sm + OFF_XH2;
    float* part  = sm + OFF_PART;
    float* part2 = sm + OFF_PART2;
    float* sw2   = sm + OFF_SW2;
    float* sw1   = sm + OFF_SW1;

    const int tid = threadIdx.x;
    unsigned rank;
    asm("mov.u32 %0, %%cluster_ctarank;" : "=r"(rank));
    const unsigned peer = rank ^ 1u;
    const int b0  = (blockIdx.x >> 1) * ROWS;

    const int nj0 = rank ? 73 : 76;
    const int jb0 = rank ? 76 : 0;
    const int nj1 = rank ? 47 : 52;
    const int jb1 = rank ? 52 : 0;

    const unsigned sbase = smem_u32(sm);
    const unsigned a_rd0 = sbase + MB_RD0 * 4;
    const unsigned a_rd1 = sbase + MB_RD1 * 4;
    const unsigned a_fl0 = sbase + MB_FL0 * 4;
    const unsigned a_fl1 = sbase + MB_FL1 * 4;

    const int mat = tid / 160;
    const int rem = tid - mat * 160;
    const int jj  = rem;
    const int rsel = (mat == 0) ? 0 : mat;

    // decomposition: L0 = 20 j-groups x 8 k-chunks(35); L1 = 13 j-groups x 12 k-chunks(21)
    const int jg0 = rem % 20, kc0 = rem / 20;
    const int kb0 = kc0 * 35;
    const int jg1 = rem % 13, kc1 = rem / 13;
    const int kb1 = kc1 * 21;
    const bool act1 = (kc1 < 12);

    // ---- prologue ----
    for (int i = tid; i < 2240; i += NTH) xh0d[i] = 0.f;
    for (int i = tid; i < 2016; i += NTH) xh1d[i] = 0.f;
    for (int i = tid; i < 448;  i += NTH) xh2[i]  = 0.f;
    for (int i = tid; i < 3 * CAT2 * S2; i += NTH) sw2[i] = ((const float*)g_W2)[i];
    // layer-1 weight slice -> SMEM: sw1[mat][k][jl], jl in [0,52)
    for (int i = tid; i < 3 * K1P * SJ1; i += NTH) {
        int mc  = i / (K1P * SJ1);
        int rkj = i - mc * (K1P * SJ1);
        int k   = rkj / SJ1, jl = rkj - k * SJ1;
        sw1[i] = g_W1[mc][k * S1 + jb1 + jl];
    }

    if (tid == 0) {
        mbar_init(a_rd0, 1);
        mbar_init(a_rd1, 1);
        mbar_init(a_fl0, 1);
        mbar_init(a_fl1, 1);
    }

    float rb1_0 = 0.f, rb2_0 = 0.f, rbc_0 = 0.f;
    float rb1_1 = 0.f, rb2_1 = 0.f, rbc_1 = 0.f;
    float rb1_2 = 0.f, rb2_2 = 0.f, rbc_2 = 0.f;
    if (jj < nj0) { rb1_0 = b1_0[jb0 + jj]; rb2_0 = b2_0[jb0 + jj]; rbc_0 = g_bc[jb0 + jj]; }
    if (jj < nj1) { rb1_1 = b1_1[jb1 + jj]; rb2_1 = b2_1[jb1 + jj]; rbc_1 = g_bc[NI + jb1 + jj]; }
    if (jj < NM)  { rb1_2 = b1_2[jj]; rb2_2 = b2_2[jj]; rbc_2 = g_bc[NI + NC + jj]; }

    // stage x_0 (duplicated pairs), prefetch x_1
    const int i0 = tid, i1 = tid + NTH;
    for (int i = tid; i < ROWS * IND; i += NTH) {
        int r = i >> 7, k = i & 127;
        float v = x[((size_t)(b0 + r) * TT + 0) * IND + k];
        *(unsigned long long*)&xh0d[k * 8 + r * 2] = pack2(v, v);
    }
    float xr0 = x[((size_t)(b0 + (i0 >> 7)) * TT + 1) * IND + (i0 & 127)];
    float xr1 = 0.f;
    if (i1 < ROWS * IND)
        xr1 = x[((size_t)(b0 + (i1 >> 7)) * TT + 1) * IND + (i1 & 127)];

    __syncthreads();
    asm volatile("barrier.cluster.arrive.aligned;" ::: "memory");
    asm volatile("barrier.cluster.wait.aligned;" ::: "memory");

    unsigned ph0 = 0, ph1 = 0, prd0 = 0, prd1 = 0;

    for (int t = 0; t < TT; ++t) {
        // ============ (a) layer-0 partials: 35 k per thread, prefetched ============
        {
            const ulonglong2* Wp =
                (const ulonglong2*)(g_W0[mat] + (size_t)kb0 * S0 + jb0 + jg0 * 4);
            const float* ab = xh0d + kb0 * 8;
            unsigned long long aA0 = 0, aB0 = 0, aA1 = 0, aB1 = 0;
            unsigned long long aA2 = 0, aB2 = 0, aA3 = 0, aB3 = 0;
            ulonglong2 wreg[5];
            #pragma unroll
            for (int i = 0; i < 5; ++i) wreg[i] = Wp[i * (S0 / 4)];
            Wp += 5 * (S0 / 4);
            #pragma unroll
            for (int b = 0; b < 7; ++b) {
                ulonglong2 wnxt[5];
                if (b + 1 < 7) {
                    #pragma unroll
                    for (int i = 0; i < 5; ++i) wnxt[i] = Wp[i * (S0 / 4)];
                    Wp += 5 * (S0 / 4);
                }
                #pragma unroll
                for (int i = 0; i < 5; ++i) {
                    ulonglong2 d01 = *(const ulonglong2*)(ab);
                    ulonglong2 d23 = *(const ulonglong2*)(ab + 4);
                    ab += 8;
                    aA0 = fma2(wreg[i].x, d01.x, aA0); aB0 = fma2(wreg[i].y, d01.x, aB0);
                    aA1 = fma2(wreg[i].x, d01.y, aA1); aB1 = fma2(wreg[i].y, d01.y, aB1);
                    aA2 = fma2(wreg[i].x, d23.x, aA2); aB2 = fma2(wreg[i].y, d23.x, aB2);
                    aA3 = fma2(wreg[i].x, d23.y, aA3); aB3 = fma2(wreg[i].y, d23.y, aB3);
                }
                if (b + 1 < 7) {
                    #pragma unroll
                    for (int i = 0; i < 5; ++i) wreg[i] = wnxt[i];
                }
            }
            float* P = part + (size_t)((kc0 * 3 + mat) * 4) * 80 + jg0 * 4;
            *(ulonglong2*)(P)       = make_ulonglong2(aA0, aB0);
            *(ulonglong2*)(P + 80)  = make_ulonglong2(aA1, aB1);
            *(ulonglong2*)(P + 160) = make_ulonglong2(aA2, aB2);
            *(ulonglong2*)(P + 240) = make_ulonglong2(aA3, aB3);
        }
        __syncthreads();
        if (tid == 0) mbar_arrive_peer(a_rd0, peer);   // "we finished reading xh0"

        // ============ (c) combine layer-0 (local j half) + exchange ============
        if (jj < nj0) {
            float a1 = 0.f, a2 = 0.f, ac = 0.f;
            #pragma unroll
            for (int c = 0; c < 8; ++c) {
                a1 += part[((c * 3 + 0) * 4 + rsel) * 80 + jj];
                a2 += part[((c * 3 + 1) * 4 + rsel) * 80 + jj];
                ac += part[((c * 3 + 2) * 4 + rsel) * 80 + jj];
            }
            float h = cfc_mix(a1, a2, ac, rb1_0, rb2_0, rbc_0);
            unsigned long long hh = pack2(h, h);
            const int jg = jb0 + jj;
            const int o0 = (IND + jg) * 8 + rsel * 2;
            const int o1 = jg * 8 + rsel * 2;
            *(unsigned long long*)&xh0d[o0] = hh;
            *(unsigned long long*)&xh1d[o1] = hh;
            float h3 = 0.f; unsigned long long hh3 = 0;
            if (mat == 0) {
                float c1 = 0.f, c2 = 0.f, cc = 0.f;
                #pragma unroll
                for (int c = 0; c < 8; ++c) {
                    c1 += part[((c * 3 + 0) * 4 + 3) * 80 + jj];
                    c2 += part[((c * 3 + 1) * 4 + 3) * 80 + jj];
                    cc += part[((c * 3 + 2) * 4 + 3) * 80 + jj];
                }
                h3 = cfc_mix(c1, c2, cc, rb1_0, rb2_0, rbc_0);
                hh3 = pack2(h3, h3);
                *(unsigned long long*)&xh0d[o0 + 6 - rsel * 2] = hh3;  // row3 slot
                *(unsigned long long*)&xh1d[o1 + 6 - rsel * 2] = hh3;
            }
            mbar_wait(a_rd0, prd0);                    // peer done reading its xh0
            st_peer_u64(sbase + (OFF_XH0 + o0) * 4, peer, hh);
            st_peer_u64(sbase + (OFF_XH1 + o1) * 4, peer, hh);
            if (mat == 0) {
                st_peer_u64(sbase + (OFF_XH0 + o0 + 6) * 4, peer, hh3);
                st_peer_u64(sbase + (OFF_XH1 + o1 + 6) * 4, peer, hh3);
            }
        }
        {   // x restage (local only; both CTAs stage full x)
            *(unsigned long long*)&xh0d[(i0 & 127) * 8 + (i0 >> 7) * 2] = pack2(xr0, xr0);
            if (i1 < ROWS * IND)
                *(unsigned long long*)&xh0d[(i1 & 127) * 8 + (i1 >> 7) * 2] = pack2(xr1, xr1);
            int tn = t + 2; if (tn > TT - 1) tn = TT - 1;
            xr0 = x[((size_t)(b0 + (i0 >> 7)) * TT + tn) * IND + (i0 & 127)];
            if (i1 < ROWS * IND)
                xr1 = x[((size_t)(b0 + (i1 >> 7)) * TT + tn) * IND + (i1 & 127)];
        }
        __syncthreads();
        if (tid == 0) fence_arrive_peer(a_fl0, peer);  // publish our half to peer
        mbar_wait(a_fl0, ph0);                         // peer's h0 half arrived
        ph0 ^= 1; prd0 ^= 1;

        // ============ (e) layer-1 partials: SMEM-resident weights ============
        if (act1) {
            const float* Wb = sw1 + mat * (K1P * SJ1) + kb1 * SJ1 + jg1 * 4;
            const float* ab = xh1d + kb1 * 8;
            unsigned long long aA0 = 0, aB0 = 0, aA1 = 0, aB1 = 0;
            unsigned long long aA2 = 0, aB2 = 0, aA3 = 0, aB3 = 0;
            #pragma unroll
            for (int k = 0; k < 21; ++k) {
                ulonglong2 w   = *(const ulonglong2*)(Wb + k * SJ1);
                ulonglong2 d01 = *(const ulonglong2*)(ab + k * 8);
                ulonglong2 d23 = *(const ulonglong2*)(ab + k * 8 + 4);
                aA0 = fma2(w.x, d01.x, aA0); aB0 = fma2(w.y, d01.x, aB0);
                aA1 = fma2(w.x, d01.y, aA1); aB1 = fma2(w.y, d01.y, aB1);
                aA2 = fma2(w.x, d23.x, aA2); aB2 = fma2(w.y, d23.x, aB2);
                aA3 = fma2(w.x, d23.y, aA3); aB3 = fma2(w.y, d23.y, aB3);
            }
            float* P = part + (size_t)((kc1 * 3 + mat) * 4) * 52 + jg1 * 4;
            *(ulonglong2*)(P)       = make_ulonglong2(aA0, aB0);
            *(ulonglong2*)(P + 52)  = make_ulonglong2(aA1, aB1);
            *(ulonglong2*)(P + 104) = make_ulonglong2(aA2, aB2);
            *(ulonglong2*)(P + 156) = make_ulonglong2(aA3, aB3);
        }
        __syncthreads();
        if (tid == 0) mbar_arrive_peer(a_rd1, peer);   // "we finished reading xh1"

        // ============ (g) combine layer-1 (local j half) + exchange ============
        if (jj < nj1) {
            float a1 = 0.f, a2 = 0.f, ac = 0.f;
            #pragma unroll
            for (int c = 0; c < 12; ++c) {
                a1 += part[((c * 3 + 0) * 4 + rsel) * 52 + jj];
                a2 += part[((c * 3 + 1) * 4 + rsel) * 52 + jj];
                ac += part[((c * 3 + 2) * 4 + rsel) * 52 + jj];
            }
            float h = cfc_mix(a1, a2, ac, rb1_1, rb2_1, rbc_1);
            unsigned long long hh = pack2(h, h);
            const int jg = jb1 + jj;
            const int o1 = (NI + jg) * 8 + rsel * 2;
            const int o2 = jg * 4 + rsel;
            *(unsigned long long*)&xh1d[o1] = hh;
            xh2[o2] = h;
            float h3 = 0.f; unsigned long long hh3 = 0;
            if (mat == 0) {
                float c1 = 0.f, c2 = 0.f, cc = 0.f;
                #pragma unroll
                for (int c = 0; c < 12; ++c) {
                    c1 += part[((c * 3 + 0) * 4 + 3) * 52 + jj];
                    c2 += part[((c * 3 + 1) * 4 + 3) * 52 + jj];
                    cc += part[((c * 3 + 2) * 4 + 3) * 52 + jj];
                }
                h3 = cfc_mix(c1, c2, cc, rb1_1, rb2_1, rbc_1);
                hh3 = pack2(h3, h3);
                *(unsigned long long*)&xh1d[(NI + jg) * 8 + 6] = hh3;
                xh2[jg * 4 + 3] = h3;
            }
            mbar_wait(a_rd1, prd1);                    // peer done reading its xh1
            st_peer_u64(sbase + (OFF_XH1 + o1) * 4, peer, hh);
            st_peer_u32(sbase + (OFF_XH2 + o2) * 4, peer, h);
            if (mat == 0) {
                st_peer_u64(sbase + (OFF_XH1 + (NI + jg) * 8 + 6) * 4, peer, hh3);
                st_peer_u32(sbase + (OFF_XH2 + jg * 4 + 3) * 4, peer, h3);
            }
        }
        __syncthreads();
        if (tid == 0) fence_arrive_peer(a_fl1, peer);  // publish our half to peer
        mbar_wait(a_fl1, ph1);                         // peer's h1 half arrived
        ph1 ^= 1; prd1 ^= 1;

        // ============ (i) layer-2 partials (redundant on both ranks) ============
        {
            int j2 = jj & 7, kc2 = jj >> 3;
            int kb = kc2 * 6;
            int ke = kb + 6; if (ke > CAT2) ke = CAT2; if (kb > CAT2) kb = CAT2;
            unsigned long long p01 = 0, p23 = 0;
            const float* W = sw2 + mat * (CAT2 * S2) + j2;
            for (int k = kb; k < ke; ++k) {
                float w = W[k * 8];
                unsigned long long ww = pack2(w, w);
                ulonglong2 u = *(const ulonglong2*)&xh2[k * 4];
                p01 = fma2(ww, u.x, p01);
                p23 = fma2(ww, u.y, p23);
            }
            *(ulonglong2*)&part2[(mat * 160 + jj) * 4] = make_ulonglong2(p01, p23);
        }
        __syncthreads();

        // ============ (k) combine layer-2 (both ranks; rank0 writes y) ============
        if (mat == 0 && jj < NM) {
            unsigned long long s0a = 0, s0b = 0, s1a = 0, s1b = 0, s2a = 0, s2b = 0;
            #pragma unroll 4
            for (int kc = 0; kc < 20; ++kc) {
                int p = (kc * 8 + jj) * 4;
                ulonglong2 u0 = *(const ulonglong2*)&part2[p];
                ulonglong2 u1 = *(const ulonglong2*)&part2[640 + p];
                ulonglong2 u2 = *(const ulonglong2*)&part2[1280 + p];
                s0a = add2(s0a, u0.x); s0b = add2(s0b, u0.y);
                s1a = add2(s1a, u1.x); s1b = add2(s1b, u1.y);
                s2a = add2(s2a, u2.x); s2b = add2(s2b, u2.y);
            }
            float a1[4], a2[4], ac[4];
            unpack2(s0a, a1[0], a1[1]); unpack2(s0b, a1[2], a1[3]);
            unpack2(s1a, a2[0], a2[1]); unpack2(s1b, a2[2], a2[3]);
            unpack2(s2a, ac[0], ac[1]); unpack2(s2b, ac[2], ac[3]);
            #pragma unroll
            for (int r = 0; r < 4; ++r) {
                float h = cfc_mix(a1[r], a2[r], ac[r], rb1_2, rb2_2, rbc_2);
                xh2[(NC + jj) * 4 + r] = h;
                if (rank == 0)
                    out[((size_t)(b0 + r) * TT + t) * NM + jj] = tanhf(h);
            }
        }
        // no barrier: next conflicting access to part2/xh2[NC+..] is several
        // barriers away (end-(a), (c) sync, fl0 wait, end-(e), fl1 wait).
    }

    __syncthreads();
    if (write_h && rank == 0) {
        size_t base = (size_t)BB * TT * NM;
        for (int pass = 0; pass < 2; ++pass) {
            int rr = (pass == 0) ? rsel : 3;
            if (pass == 1 && mat != 0) break;
            size_t ro = base + (size_t)(b0 + rr) * 256;
            if (jj < NI) out[ro + jj]           = xh0d[(IND + jj) * 8 + rr * 2];
            if (jj < NC) out[ro + NI + jj]      = xh1d[(NI + jj) * 8 + rr * 2];
            if (jj < NM) out[ro + NI + NC + jj] = xh2[(NC + jj) * 4 + rr];
        }
    }
    asm volatile("barrier.cluster.arrive.aligned;" ::: "memory");
    asm volatile("barrier.cluster.wait.aligned;" ::: "memory");
}

// ---------------------------------------------------------------------------
extern "C" void kernel_launch(void* const* d_in, const int* in_sizes, int n_in,
                              void* d_out, int out_size)
{
    const float *x, *dt;
    const float *w1[3], *b1[3], *w2[3], *b2[3], *wa[3], *ba[3], *wb[3], *bb[3];
    const int   *m[3];

    if (in_sizes[0] == BB * TT * IND) {
        x  = (const float*)d_in[0];
        dt = (const float*)d_in[1];
        for (int l = 0; l < 3; l++) {
            int base = 2 + 9 * l;
            w1[l] = (const float*)d_in[base + 0];
            b1[l] = (const float*)d_in[base + 1];
            w2[l] = (const float*)d_in[base + 2];
            b2[l] = (const float*)d_in[base + 3];
            wa[l] = (const float*)d_in[base + 4];
            ba[l] = (const float*)d_in[base + 5];
            wb[l] = (const float*)d_in[base + 6];
            bb[l] = (const float*)d_in[base + 7];
            m[l]  = (const int*)  d_in[base + 8];
        }
    } else {
        for (int l = 0; l < 3; l++) {
            int base = 9 * l;
            w1[l] = (const float*)d_in[base + 0];
            w2[l] = (const float*)d_in[base + 1];
            wa[l] = (const float*)d_in[base + 2];
            wb[l] = (const float*)d_in[base + 3];
            b1[l] = (const float*)d_in[base + 4];
            b2[l] = (const float*)d_in[base + 5];
            ba[l] = (const float*)d_in[base + 6];
            bb[l] = (const float*)d_in[base + 7];
            m[l]  = (const int*)  d_in[base + 8];
        }
        x  = (const float*)d_in[27];
        dt = (const float*)d_in[28];
    }

    cfc_precompute_kernel<<<148, 256>>>(
        w1[0], w2[0], wa[0], wb[0], ba[0], bb[0], m[0],
        w1[1], w2[1], wa[1], wb[1], ba[1], bb[1], m[1],
        w1[2], w2[2], wa[2], wb[2], ba[2], bb[2], m[2],
        dt);

    cudaFuncSetAttribute(cfc_main_kernel,
                         cudaFuncAttributeMaxDynamicSharedMemorySize, SMEM_BYTES);

    int write_h = (out_size >= BB * TT * NM + BB * 256) ? 1 : 0;
    cfc_main_kernel<<<(BB / ROWS) * 2, NTH, SMEM_BYTES>>>(
        x, b1[0], b2[0], b1[1], b2[1], b1[2], b2[2],
        (float*)d_out, write_h);
}